// round 15
// baseline (speedup 1.0000x reference)
#include <cuda_runtime.h>
#include <cuda_fp16.h>
#include <math.h>
#include <stdint.h>

#define BATCH   16
#define CH      512
#define HW_     1024
#define NGROUPS 8
#define CG      64
#define NH      8
#define HD      64
#define EPS_    1e-5f
#define QSC_    0.18033688f   // 0.125 * log2(e): softmax done in exp2 domain

// Scratch (allocation-free) — fp16 intermediates
__device__ __half g_xn [BATCH*CH*HW_];
__device__ __half g_qkv[(size_t)BATCH*3*CH*HW_];
__device__ __half g_att[BATCH*CH*HW_];
__device__ __half g_wq [3*CH*CH];
__device__ __half g_wp [CH*CH];

// ---------------------------------------------------------------------------
// helpers
// ---------------------------------------------------------------------------
__device__ __forceinline__ uint32_t sptr(const void* p) {
    return (uint32_t)__cvta_generic_to_shared(p);
}
__device__ __forceinline__ uint32_t packh(float a, float b) {
    __half2 t = __float22half2_rn(make_float2(a, b));
    return *(uint32_t*)&t;
}
__device__ __forceinline__ uint32_t exp2h2(float a, float b) {
    __half2 h = __float22half2_rn(make_float2(a, b));
    h = h2exp2(h);
    return *(uint32_t*)&h;
}
__device__ __forceinline__ void cpa16(uint32_t s, const void* g) {
    asm volatile("cp.async.cg.shared.global [%0],[%1],16;" :: "r"(s), "l"(g));
}
#define CP_COMMIT() asm volatile("cp.async.commit_group;")
#define CP_WAIT(n)  asm volatile("cp.async.wait_group %0;" :: "n"(n))

__device__ __forceinline__ void ldsm4(uint32_t* r, uint32_t a) {
    asm volatile("ldmatrix.sync.aligned.m8n8.x4.shared.b16 {%0,%1,%2,%3},[%4];"
        : "=r"(r[0]), "=r"(r[1]), "=r"(r[2]), "=r"(r[3]) : "r"(a));
}
__device__ __forceinline__ void ldsm4t(uint32_t* r, uint32_t a) {
    asm volatile("ldmatrix.sync.aligned.m8n8.x4.trans.shared.b16 {%0,%1,%2,%3},[%4];"
        : "=r"(r[0]), "=r"(r[1]), "=r"(r[2]), "=r"(r[3]) : "r"(a));
}
__device__ __forceinline__ void mma_f16(float* c, const uint32_t* a, const uint32_t* b) {
    asm volatile("mma.sync.aligned.m16n8k16.row.col.f32.f16.f16.f32 "
        "{%0,%1,%2,%3},{%4,%5,%6,%7},{%8,%9},{%0,%1,%2,%3};"
        : "+f"(c[0]), "+f"(c[1]), "+f"(c[2]), "+f"(c[3])
        : "r"(a[0]), "r"(a[1]), "r"(a[2]), "r"(a[3]), "r"(b[0]), "r"(b[1]));
}

// ---------------------------------------------------------------------------
// fp32 -> fp16 weight conversion
// ---------------------------------------------------------------------------
__global__ void f2h_kernel(const float* __restrict__ src,
                           __half* __restrict__ dst, int n)
{
    int i = (blockIdx.x*blockDim.x + threadIdx.x) * 4;
    if (i < n) {
        float4 v = *(const float4*)&src[i];
        uint2 o;
        o.x = packh(v.x, v.y);
        o.y = packh(v.z, v.w);
        *(uint2*)&dst[i] = o;
    }
}

// ---------------------------------------------------------------------------
// GroupNorm -> fp16
// ---------------------------------------------------------------------------
__global__ void groupnorm_kernel(const float* __restrict__ x,
                                 const float* __restrict__ w,
                                 const float* __restrict__ bias,
                                 __half* __restrict__ xn)
{
    int bg = blockIdx.x;
    int bb = bg / NGROUPS, g = bg % NGROUPS;
    const float* xp = x  + ((size_t)bb*CH + g*CG) * HW_;
    __half*      op = xn + ((size_t)bb*CH + g*CG) * HW_;
    const int NEL = CG * HW_;
    int tid = threadIdx.x;

    float s = 0.f, ss = 0.f;
    for (int i = tid*4; i < NEL; i += blockDim.x*4) {
        float4 v = *(const float4*)&xp[i];
        s  += v.x + v.y + v.z + v.w;
        ss += v.x*v.x + v.y*v.y + v.z*v.z + v.w*v.w;
    }
    __shared__ float r1[1024], r2[1024];
    r1[tid] = s; r2[tid] = ss;
    __syncthreads();
    for (int st = 512; st > 0; st >>= 1) {
        if (tid < st) { r1[tid] += r1[tid+st]; r2[tid] += r2[tid+st]; }
        __syncthreads();
    }
    float mean = r1[0] * (1.f/NEL);
    float var  = r2[0] * (1.f/NEL) - mean*mean;
    float inv  = rsqrtf(var + EPS_);

    for (int i = tid*4; i < NEL; i += blockDim.x*4) {
        int ch = g*CG + (i >> 10);
        float wc = w[ch], bc = bias[ch];
        float4 v = *(const float4*)&xp[i];
        uint2 o;
        o.x = packh((v.x - mean)*inv*wc + bc, (v.y - mean)*inv*wc + bc);
        o.y = packh((v.z - mean)*inv*wc + bc, (v.w - mean)*inv*wc + bc);
        *(uint2*)&op[i] = o;
    }
}

// ---------------------------------------------------------------------------
// fp16 MMA GEMM: 128x256x32 tile, 512 threads = 16 warps (4x4), warp 32x64.
// (R14 structure, fp16 element type.)
// ---------------------------------------------------------------------------
#define GBM 128
#define GBN 256
#define GBK 32
#define ASTR 40
#define BSTR 264
#define A_ST (GBM*ASTR)
#define B_ST (GBK*BSTR)
#define GEMM_SMEM ((4*(A_ST + B_ST)) * 2)    // 108544 B

template<bool OUT_HALF>
__global__ __launch_bounds__(512, 1)
void mma_gemm_kernel(const __half* __restrict__ A,
                     const __half* __restrict__ Bbase,
                     void* __restrict__ Cbase,
                     const float* __restrict__ bias,
                     const float* __restrict__ Rbase,
                     int M, int K, int N, int q_rows)
{
    extern __shared__ __align__(16) uint16_t smg[];
    uint16_t* As = smg;              // [4][128*40]
    uint16_t* Bs = smg + 4*A_ST;     // [4][32*264]

    int bz = blockIdx.z;
    const __half* Bm = Bbase + (size_t)bz * K * N;

    int m0 = blockIdx.y * GBM, n0 = blockIdx.x * GBN;
    int tid = threadIdx.x, lane = tid & 31, warp = tid >> 5;
    int wm = (warp >> 2) * 32, wn = (warp & 3) * 64;

    int arow = tid >> 2,  acol = (tid & 3) * 8;
    int brow = tid >> 5,  bcol = (tid & 31) * 8;

    const __half* Ab  = A + (size_t)(m0 + arow)*K + acol;
    const __half* Bb0 = Bm + (size_t)brow*N      + n0 + bcol;
    const __half* Bb1 = Bm + (size_t)(brow+16)*N + n0 + bcol;

    float c[2][8][4];
    #pragma unroll
    for (int mt = 0; mt < 2; mt++)
        #pragma unroll
        for (int nt = 0; nt < 8; nt++)
            #pragma unroll
            for (int e = 0; e < 4; e++) c[mt][nt][e] = 0.f;

    const int KT = K / GBK;

    #pragma unroll
    for (int p = 0; p < 3; p++) {
        int st = p, k0 = p * GBK;
        cpa16(sptr(&As[st*A_ST + arow*ASTR + acol]), Ab + k0);
        cpa16(sptr(&Bs[st*B_ST + brow*BSTR + bcol]),      Bb0 + (size_t)k0*N);
        cpa16(sptr(&Bs[st*B_ST + (brow+16)*BSTR + bcol]), Bb1 + (size_t)k0*N);
        CP_COMMIT();
    }

    for (int kt = 0; kt < KT; kt++) {
        CP_WAIT(2);
        __syncthreads();

        const uint16_t* Ac = As + (kt & 3)*A_ST;
        const uint16_t* Bc = Bs + (kt & 3)*B_ST;

        #pragma unroll
        for (int ks = 0; ks < 2; ks++) {
            uint32_t a[2][4], b[4][4];
            int g = lane >> 3;
            #pragma unroll
            for (int mt = 0; mt < 2; mt++) {
                int row = wm + mt*16 + (g & 1)*8 + (lane & 7);
                int col = ks*16 + (g >> 1)*8;
                ldsm4(a[mt], sptr(&Ac[row*ASTR + col]));
            }
            int kk = ks*16 + (lane & 15);
            int cb = (lane >> 4)*8;
            #pragma unroll
            for (int ntp = 0; ntp < 4; ntp++)
                ldsm4t(b[ntp], sptr(&Bc[kk*BSTR + wn + ntp*16 + cb]));
            #pragma unroll
            for (int mt = 0; mt < 2; mt++)
                #pragma unroll
                for (int ntp = 0; ntp < 4; ntp++) {
                    mma_f16(c[mt][2*ntp],   a[mt], &b[ntp][0]);
                    mma_f16(c[mt][2*ntp+1], a[mt], &b[ntp][2]);
                }
        }

        if (kt + 3 < KT) {
            int st = (kt + 3) & 3, k0 = (kt + 3) * GBK;
            cpa16(sptr(&As[st*A_ST + arow*ASTR + acol]), Ab + k0);
            cpa16(sptr(&Bs[st*B_ST + brow*BSTR + bcol]),      Bb0 + (size_t)k0*N);
            cpa16(sptr(&Bs[st*B_ST + (brow+16)*BSTR + bcol]), Bb1 + (size_t)k0*N);
        }
        CP_COMMIT();
    }

    #pragma unroll
    for (int mt = 0; mt < 2; mt++) {
        #pragma unroll
        for (int half = 0; half < 2; half++) {
            int m = m0 + wm + mt*16 + (lane >> 2) + half*8;
            float bv = bias ? bias[m] : 0.f;
            #pragma unroll
            for (int nt = 0; nt < 8; nt++) {
                int n = n0 + wn + nt*8 + 2*(lane & 3);
                float x0 = c[mt][nt][half*2 + 0] + bv;
                float x1 = c[mt][nt][half*2 + 1] + bv;
                if (OUT_HALF) {
                    float sc = (m < q_rows) ? QSC_ : 1.0f;
                    *(uint32_t*)((__half*)Cbase + (size_t)bz*M*N + (size_t)m*N + n)
                        = packh(x0*sc, x1*sc);
                } else {
                    float2 o = make_float2(x0, x1);
                    if (Rbase) {
                        float2 r = *(const float2*)&Rbase[(size_t)bz*M*N + (size_t)m*N + n];
                        o.x += r.x; o.y += r.y;
                    }
                    *(float2*)((float*)Cbase + (size_t)bz*M*N + (size_t)m*N + n) = o;
                }
            }
        }
    }
}

// ---------------------------------------------------------------------------
// Flash attention: 128 queries/block, 4 warps, 2 q-tiles share K/V frags,
// 3-stage cp.async, fp16 path: ex2.f16x2 softmax, P as f16 A-frags direct,
// row-sums via ones-vector MMA (no shuffle reductions for l).
// ---------------------------------------------------------------------------
#define KSTR 72
#define QSTR2 136
#define OFF_KS (64*QSTR2)
#define OFF_VS (OFF_KS + 3*64*KSTR)
#define ATT_SMEM_HALVES (OFF_VS + 3*64*KSTR)
#define ATT_SMEM (ATT_SMEM_HALVES * 2)         // 72704 B

__global__ __launch_bounds__(128)
void attention_kernel(const __half* __restrict__ qkv,
                      __half* __restrict__ outp)
{
    extern __shared__ __align__(16) uint16_t sm[];
    uint16_t* Qs = sm;            // [64][136] — Q stage, then O stage
    uint16_t* Ks = sm + OFF_KS;   // [3][64][72]
    uint16_t* Vs = sm + OFF_VS;   // [3][64][72]

    int bh = blockIdx.y;
    int bb = bh >> 3, hh = bh & 7;
    int i0 = blockIdx.x * 128;
    const __half* qp = qkv + ((size_t)bb*3*CH + hh*HD) * HW_;
    const __half* kp = qp + (size_t)CH * HW_;
    const __half* vp = qp + (size_t)2*CH * HW_;

    int tid = threadIdx.x, lane = tid & 31, warp = tid >> 5;

    #pragma unroll
    for (int r = 0; r < 8; r++) {
        int idx = r*128 + tid;
        int d = idx >> 4, cc = (idx & 15) * 8;
        cpa16(sptr(&Qs[d*QSTR2 + cc]), qp + (size_t)d*HW_ + i0 + cc);
    }
    #pragma unroll
    for (int r = 0; r < 4; r++) {
        int idx = r*128 + tid;
        int d = idx >> 3, cc = (idx & 7) * 8;
        cpa16(sptr(&Ks[d*KSTR + cc]), kp + (size_t)d*HW_ + cc);
        cpa16(sptr(&Vs[d*KSTR + cc]), vp + (size_t)d*HW_ + cc);
    }
    CP_COMMIT();
    #pragma unroll
    for (int r = 0; r < 4; r++) {
        int idx = r*128 + tid;
        int d = idx >> 3, cc = (idx & 7) * 8;
        cpa16(sptr(&Ks[64*KSTR + d*KSTR + cc]), kp + (size_t)d*HW_ + 64 + cc);
        cpa16(sptr(&Vs[64*KSTR + d*KSTR + cc]), vp + (size_t)d*HW_ + 64 + cc);
    }
    CP_COMMIT();

    const uint32_t ONE2 = 0x3C003C00u;           // half2(1,1)
    const uint32_t bones[2] = {ONE2, ONE2};

    uint32_t qf[2][4][4];
    float mx[2][2], l[2][2];
    float o[2][8][4];
    #pragma unroll
    for (int t = 0; t < 2; t++) {
        mx[t][0] = mx[t][1] = -1e30f;
        l[t][0] = l[t][1] = 0.f;
        #pragma unroll
        for (int nt = 0; nt < 8; nt++)
            #pragma unroll
            for (int e = 0; e < 4; e++) o[t][nt][e] = 0.f;
    }

    for (int jt = 0; jt < 16; jt++) {
        CP_WAIT(1);
        __syncthreads();

        if (jt == 0) {   // Q frags (register-resident afterwards)
            int g = lane >> 3;
            int kq = (g >> 1)*8 + (lane & 7);
            #pragma unroll
            for (int t = 0; t < 2; t++) {
                int mq = t*64 + warp*16 + (g & 1)*8;
                #pragma unroll
                for (int ks = 0; ks < 4; ks++)
                    ldsm4t(qf[t][ks], sptr(&Qs[(ks*16 + kq)*QSTR2 + mq]));
            }
        }

        const uint16_t* Kc = Ks + (jt % 3)*64*KSTR;
        const uint16_t* Vc = Vs + (jt % 3)*64*KSTR;

        // S = Q K^T (both q-tiles share K frags)
        float s[2][8][4];
        #pragma unroll
        for (int t = 0; t < 2; t++)
            #pragma unroll
            for (int nt = 0; nt < 8; nt++)
                #pragma unroll
                for (int e = 0; e < 4; e++) s[t][nt][e] = 0.f;

        #pragma unroll
        for (int ks = 0; ks < 4; ks++) {
            int kk = ks*16 + (lane & 15);
            int cb = (lane >> 4)*8;
            #pragma unroll
            for (int ntp = 0; ntp < 4; ntp++) {
                uint32_t b[4];
                ldsm4t(b, sptr(&Kc[kk*KSTR + ntp*16 + cb]));
                #pragma unroll
                for (int t = 0; t < 2; t++) {
                    mma_f16(s[t][2*ntp],   qf[t][ks], &b[0]);
                    mma_f16(s[t][2*ntp+1], qf[t][ks], &b[2]);
                }
            }
        }

        // online softmax: rmax (fp32 + shfl), then exp via ex2.f16x2 -> P frags
        uint32_t pah[2][4][4];
        #pragma unroll
        for (int t = 0; t < 2; t++) {
            float rmax0 = -1e30f, rmax1 = -1e30f;
            #pragma unroll
            for (int nt = 0; nt < 8; nt++) {
                rmax0 = fmaxf(rmax0, fmaxf(s[t][nt][0], s[t][nt][1]));
                rmax1 = fmaxf(rmax1, fmaxf(s[t][nt][2], s[t][nt][3]));
            }
            #pragma unroll
            for (int off = 1; off < 4; off <<= 1) {
                rmax0 = fmaxf(rmax0, __shfl_xor_sync(0xffffffffu, rmax0, off));
                rmax1 = fmaxf(rmax1, __shfl_xor_sync(0xffffffffu, rmax1, off));
            }
            float mn0 = fmaxf(mx[t][0], rmax0), mn1 = fmaxf(mx[t][1], rmax1);
            float corr0 = exp2f(mx[t][0] - mn0), corr1 = exp2f(mx[t][1] - mn1);
            mx[t][0] = mn0; mx[t][1] = mn1;

            #pragma unroll
            for (int nt = 0; nt < 8; nt++) {
                pah[t][nt >> 1][(nt & 1)*2 + 0] =
                    exp2h2(s[t][nt][0] - mn0, s[t][nt][1] - mn0);
                pah[t][nt >> 1][(nt & 1)*2 + 1] =
                    exp2h2(s[t][nt][2] - mn1, s[t][nt][3] - mn1);
            }

            // row sums via ones-MMA: ls[0]=sum row r0, ls[2]=sum row r0+8
            float ls[4] = {0.f, 0.f, 0.f, 0.f};
            #pragma unroll
            for (int ks = 0; ks < 4; ks++)
                mma_f16(ls, pah[t][ks], bones);

            l[t][0] = l[t][0]*corr0 + ls[0];
            l[t][1] = l[t][1]*corr1 + ls[2];
            #pragma unroll
            for (int nt = 0; nt < 8; nt++) {
                o[t][nt][0] *= corr0; o[t][nt][1] *= corr0;
                o[t][nt][2] *= corr1; o[t][nt][3] *= corr1;
            }
        }

        // O += P @ V — P A-frags directly from f16x2 exp results
        #pragma unroll
        for (int ks = 0; ks < 4; ks++) {
            int jc = ks*16 + ((lane >> 3) & 1)*8;
            int dbase = (lane >> 4)*8 + (lane & 7);
            #pragma unroll
            for (int ntp = 0; ntp < 4; ntp++) {
                uint32_t b[4];
                ldsm4(b, sptr(&Vc[(ntp*16 + dbase)*KSTR + jc]));
                #pragma unroll
                for (int t = 0; t < 2; t++) {
                    mma_f16(o[t][2*ntp],   pah[t][ks], &b[0]);
                    mma_f16(o[t][2*ntp+1], pah[t][ks], &b[2]);
                }
            }
        }

        if (jt + 2 < 16) {
            int stp = (jt + 2) % 3;
            int j0 = (jt + 2) * 64;
            #pragma unroll
            for (int r = 0; r < 4; r++) {
                int idx = r*128 + tid;
                int d = idx >> 3, cc = (idx & 7) * 8;
                cpa16(sptr(&Ks[stp*64*KSTR + d*KSTR + cc]), kp + (size_t)d*HW_ + j0 + cc);
                cpa16(sptr(&Vs[stp*64*KSTR + d*KSTR + cc]), vp + (size_t)d*HW_ + j0 + cc);
            }
        }
        CP_COMMIT();
    }

    // normalize + stage O as fp16 [d][i] into Qs (Q long consumed)
    __syncthreads();
    {
        __half* Od = (__half*)Qs;
        #pragma unroll
        for (int t = 0; t < 2; t++) {
            float inv0 = 1.f / l[t][0], inv1 = 1.f / l[t][1];
            int iq = t*64 + warp*16 + (lane >> 2);
            #pragma unroll
            for (int nt = 0; nt < 8; nt++) {
                int d = nt*8 + 2*(lane & 3);
                Od[(size_t)d*QSTR2 + iq]         = __float2half_rn(o[t][nt][0]*inv0);
                Od[(size_t)(d+1)*QSTR2 + iq]     = __float2half_rn(o[t][nt][1]*inv0);
                Od[(size_t)d*QSTR2 + iq + 8]     = __float2half_rn(o[t][nt][2]*inv1);
                Od[(size_t)(d+1)*QSTR2 + iq + 8] = __float2half_rn(o[t][nt][3]*inv1);
            }
        }
    }
    __syncthreads();

    __half* ob = outp + ((size_t)bb*CH + hh*HD) * HW_;
    #pragma unroll
    for (int r = 0; r < 8; r++) {
        int idx = r*128 + tid;
        int d = idx >> 4, cc = (idx & 15) * 8;
        *(uint4*)&ob[(size_t)d*HW_ + i0 + cc] = *(const uint4*)&Qs[d*QSTR2 + cc];
    }
}

// ---------------------------------------------------------------------------
extern "C" void kernel_launch(void* const* d_in, const int* in_sizes, int n_in,
                              void* d_out, int out_size)
{
    const float* x      = (const float*)d_in[0];
    const float* gn_w   = (const float*)d_in[1];
    const float* gn_b   = (const float*)d_in[2];
    const float* qkv_w  = (const float*)d_in[3];
    const float* qkv_b  = (const float*)d_in[4];
    const float* proj_w = (const float*)d_in[5];
    const float* proj_b = (const float*)d_in[6];
    float* out = (float*)d_out;

    __half *xn, *qkvb, *att, *wq, *wp;
    cudaGetSymbolAddress((void**)&xn,   g_xn);
    cudaGetSymbolAddress((void**)&qkvb, g_qkv);
    cudaGetSymbolAddress((void**)&att,  g_att);
    cudaGetSymbolAddress((void**)&wq,   g_wq);
    cudaGetSymbolAddress((void**)&wp,   g_wp);

    cudaFuncSetAttribute(mma_gemm_kernel<true>,
                         cudaFuncAttributeMaxDynamicSharedMemorySize, GEMM_SMEM);
    cudaFuncSetAttribute(mma_gemm_kernel<false>,
                         cudaFuncAttributeMaxDynamicSharedMemorySize, GEMM_SMEM);
    cudaFuncSetAttribute(attention_kernel,
                         cudaFuncAttributeMaxDynamicSharedMemorySize, ATT_SMEM);

    // 0) weights fp32 -> fp16
    f2h_kernel<<<(3*CH*CH/4 + 255)/256, 256>>>(qkv_w, wq, 3*CH*CH);
    f2h_kernel<<<(CH*CH/4 + 255)/256, 256>>>(proj_w, wp, CH*CH);

    // 1) GroupNorm -> fp16
    groupnorm_kernel<<<BATCH*NGROUPS, 1024>>>(x, gn_w, gn_b, xn);

    // 2) qkv GEMM (fp16 out, q rows pre-scaled by 0.125*log2e)
    mma_gemm_kernel<true><<<dim3(HW_/GBN, (3*CH)/GBM, BATCH), 512, GEMM_SMEM>>>(
        wq, xn, qkvb, qkv_b, (const float*)0, 3*CH, CH, HW_, CH);

    // 3) flash attention (fp16, ex2.f16x2 softmax, ones-MMA row sums)
    attention_kernel<<<dim3(HW_/128, BATCH*NH), 128, ATT_SMEM>>>(qkvb, att);

    // 4) proj GEMM (fp32 out + bias + residual)
    mma_gemm_kernel<false><<<dim3(HW_/GBN, CH/GBM, BATCH), 512, GEMM_SMEM>>>(
        wp, att, out, proj_b, x, CH, CH, HW_, 0);
}

// round 16
// speedup vs baseline: 1.0080x; 1.0080x over previous
#include <cuda_runtime.h>
#include <cuda_fp16.h>
#include <math.h>
#include <stdint.h>

#define BATCH   16
#define CH      512
#define HW_     1024
#define NGROUPS 8
#define CG      64
#define NH      8
#define HD      64
#define EPS_    1e-5f
#define QSC_    0.18033688f   // 0.125 * log2(e): softmax done in exp2 domain

// Scratch (allocation-free) — fp16 intermediates
__device__ __half g_xn [BATCH*CH*HW_];
__device__ __half g_qkv[(size_t)BATCH*3*CH*HW_];
__device__ __half g_att[BATCH*CH*HW_];
__device__ __half g_wq [3*CH*CH];
__device__ __half g_wp [CH*CH];

// ---------------------------------------------------------------------------
// helpers
// ---------------------------------------------------------------------------
__device__ __forceinline__ uint32_t sptr(const void* p) {
    return (uint32_t)__cvta_generic_to_shared(p);
}
__device__ __forceinline__ uint32_t packh(float a, float b) {
    __half2 t = __float22half2_rn(make_float2(a, b));
    return *(uint32_t*)&t;
}
__device__ __forceinline__ uint32_t exp2h2(float a, float b) {
    __half2 h = __float22half2_rn(make_float2(a, b));
    h = h2exp2(h);
    return *(uint32_t*)&h;
}
__device__ __forceinline__ void cpa16(uint32_t s, const void* g) {
    asm volatile("cp.async.cg.shared.global [%0],[%1],16;" :: "r"(s), "l"(g));
}
#define CP_COMMIT() asm volatile("cp.async.commit_group;")
#define CP_WAIT(n)  asm volatile("cp.async.wait_group %0;" :: "n"(n))

__device__ __forceinline__ void ldsm4(uint32_t* r, uint32_t a) {
    asm volatile("ldmatrix.sync.aligned.m8n8.x4.shared.b16 {%0,%1,%2,%3},[%4];"
        : "=r"(r[0]), "=r"(r[1]), "=r"(r[2]), "=r"(r[3]) : "r"(a));
}
__device__ __forceinline__ void ldsm4t(uint32_t* r, uint32_t a) {
    asm volatile("ldmatrix.sync.aligned.m8n8.x4.trans.shared.b16 {%0,%1,%2,%3},[%4];"
        : "=r"(r[0]), "=r"(r[1]), "=r"(r[2]), "=r"(r[3]) : "r"(a));
}
__device__ __forceinline__ void mma_f16(float* c, const uint32_t* a, const uint32_t* b) {
    asm volatile("mma.sync.aligned.m16n8k16.row.col.f32.f16.f16.f32 "
        "{%0,%1,%2,%3},{%4,%5,%6,%7},{%8,%9},{%0,%1,%2,%3};"
        : "+f"(c[0]), "+f"(c[1]), "+f"(c[2]), "+f"(c[3])
        : "r"(a[0]), "r"(a[1]), "r"(a[2]), "r"(a[3]), "r"(b[0]), "r"(b[1]));
}

// ---------------------------------------------------------------------------
// fp32 -> fp16 weight conversion
// ---------------------------------------------------------------------------
__global__ void f2h_kernel(const float* __restrict__ src,
                           __half* __restrict__ dst, int n)
{
    int i = (blockIdx.x*blockDim.x + threadIdx.x) * 4;
    if (i < n) {
        float4 v = *(const float4*)&src[i];
        uint2 o;
        o.x = packh(v.x, v.y);
        o.y = packh(v.z, v.w);
        *(uint2*)&dst[i] = o;
    }
}

// ---------------------------------------------------------------------------
// GroupNorm -> fp16
// ---------------------------------------------------------------------------
__global__ void groupnorm_kernel(const float* __restrict__ x,
                                 const float* __restrict__ w,
                                 const float* __restrict__ bias,
                                 __half* __restrict__ xn)
{
    int bg = blockIdx.x;
    int bb = bg / NGROUPS, g = bg % NGROUPS;
    const float* xp = x  + ((size_t)bb*CH + g*CG) * HW_;
    __half*      op = xn + ((size_t)bb*CH + g*CG) * HW_;
    const int NEL = CG * HW_;
    int tid = threadIdx.x;

    float s = 0.f, ss = 0.f;
    for (int i = tid*4; i < NEL; i += blockDim.x*4) {
        float4 v = *(const float4*)&xp[i];
        s  += v.x + v.y + v.z + v.w;
        ss += v.x*v.x + v.y*v.y + v.z*v.z + v.w*v.w;
    }
    __shared__ float r1[1024], r2[1024];
    r1[tid] = s; r2[tid] = ss;
    __syncthreads();
    for (int st = 512; st > 0; st >>= 1) {
        if (tid < st) { r1[tid] += r1[tid+st]; r2[tid] += r2[tid+st]; }
        __syncthreads();
    }
    float mean = r1[0] * (1.f/NEL);
    float var  = r2[0] * (1.f/NEL) - mean*mean;
    float inv  = rsqrtf(var + EPS_);

    for (int i = tid*4; i < NEL; i += blockDim.x*4) {
        int ch = g*CG + (i >> 10);
        float wc = w[ch], bc = bias[ch];
        float4 v = *(const float4*)&xp[i];
        uint2 o;
        o.x = packh((v.x - mean)*inv*wc + bc, (v.y - mean)*inv*wc + bc);
        o.y = packh((v.z - mean)*inv*wc + bc, (v.w - mean)*inv*wc + bc);
        *(uint2*)&op[i] = o;
    }
}

// ---------------------------------------------------------------------------
// fp16 MMA GEMM: 128x256x32 tile, 512 threads = 16 warps (4x4), warp 32x64.
// ---------------------------------------------------------------------------
#define GBM 128
#define GBN 256
#define GBK 32
#define ASTR 40
#define BSTR 264
#define A_ST (GBM*ASTR)
#define B_ST (GBK*BSTR)
#define GEMM_SMEM ((4*(A_ST + B_ST)) * 2)    // 108544 B

template<bool OUT_HALF>
__global__ __launch_bounds__(512, 1)
void mma_gemm_kernel(const __half* __restrict__ A,
                     const __half* __restrict__ Bbase,
                     void* __restrict__ Cbase,
                     const float* __restrict__ bias,
                     const float* __restrict__ Rbase,
                     int M, int K, int N, int q_rows)
{
    extern __shared__ __align__(16) uint16_t smg[];
    uint16_t* As = smg;              // [4][128*40]
    uint16_t* Bs = smg + 4*A_ST;     // [4][32*264]

    int bz = blockIdx.z;
    const __half* Bm = Bbase + (size_t)bz * K * N;

    int m0 = blockIdx.y * GBM, n0 = blockIdx.x * GBN;
    int tid = threadIdx.x, lane = tid & 31, warp = tid >> 5;
    int wm = (warp >> 2) * 32, wn = (warp & 3) * 64;

    int arow = tid >> 2,  acol = (tid & 3) * 8;
    int brow = tid >> 5,  bcol = (tid & 31) * 8;

    const __half* Ab  = A + (size_t)(m0 + arow)*K + acol;
    const __half* Bb0 = Bm + (size_t)brow*N      + n0 + bcol;
    const __half* Bb1 = Bm + (size_t)(brow+16)*N + n0 + bcol;

    float c[2][8][4];
    #pragma unroll
    for (int mt = 0; mt < 2; mt++)
        #pragma unroll
        for (int nt = 0; nt < 8; nt++)
            #pragma unroll
            for (int e = 0; e < 4; e++) c[mt][nt][e] = 0.f;

    const int KT = K / GBK;

    #pragma unroll
    for (int p = 0; p < 3; p++) {
        int st = p, k0 = p * GBK;
        cpa16(sptr(&As[st*A_ST + arow*ASTR + acol]), Ab + k0);
        cpa16(sptr(&Bs[st*B_ST + brow*BSTR + bcol]),      Bb0 + (size_t)k0*N);
        cpa16(sptr(&Bs[st*B_ST + (brow+16)*BSTR + bcol]), Bb1 + (size_t)k0*N);
        CP_COMMIT();
    }

    for (int kt = 0; kt < KT; kt++) {
        CP_WAIT(2);
        __syncthreads();

        const uint16_t* Ac = As + (kt & 3)*A_ST;
        const uint16_t* Bc = Bs + (kt & 3)*B_ST;

        #pragma unroll
        for (int ks = 0; ks < 2; ks++) {
            uint32_t a[2][4], b[4][4];
            int g = lane >> 3;
            #pragma unroll
            for (int mt = 0; mt < 2; mt++) {
                int row = wm + mt*16 + (g & 1)*8 + (lane & 7);
                int col = ks*16 + (g >> 1)*8;
                ldsm4(a[mt], sptr(&Ac[row*ASTR + col]));
            }
            int kk = ks*16 + (lane & 15);
            int cb = (lane >> 4)*8;
            #pragma unroll
            for (int ntp = 0; ntp < 4; ntp++)
                ldsm4t(b[ntp], sptr(&Bc[kk*BSTR + wn + ntp*16 + cb]));
            #pragma unroll
            for (int mt = 0; mt < 2; mt++)
                #pragma unroll
                for (int ntp = 0; ntp < 4; ntp++) {
                    mma_f16(c[mt][2*ntp],   a[mt], &b[ntp][0]);
                    mma_f16(c[mt][2*ntp+1], a[mt], &b[ntp][2]);
                }
        }

        if (kt + 3 < KT) {
            int st = (kt + 3) & 3, k0 = (kt + 3) * GBK;
            cpa16(sptr(&As[st*A_ST + arow*ASTR + acol]), Ab + k0);
            cpa16(sptr(&Bs[st*B_ST + brow*BSTR + bcol]),      Bb0 + (size_t)k0*N);
            cpa16(sptr(&Bs[st*B_ST + (brow+16)*BSTR + bcol]), Bb1 + (size_t)k0*N);
        }
        CP_COMMIT();
    }

    #pragma unroll
    for (int mt = 0; mt < 2; mt++) {
        #pragma unroll
        for (int half = 0; half < 2; half++) {
            int m = m0 + wm + mt*16 + (lane >> 2) + half*8;
            float bv = bias ? bias[m] : 0.f;
            #pragma unroll
            for (int nt = 0; nt < 8; nt++) {
                int n = n0 + wn + nt*8 + 2*(lane & 3);
                float x0 = c[mt][nt][half*2 + 0] + bv;
                float x1 = c[mt][nt][half*2 + 1] + bv;
                if (OUT_HALF) {
                    float sc = (m < q_rows) ? QSC_ : 1.0f;
                    *(uint32_t*)((__half*)Cbase + (size_t)bz*M*N + (size_t)m*N + n)
                        = packh(x0*sc, x1*sc);
                } else {
                    float2 o = make_float2(x0, x1);
                    if (Rbase) {
                        float2 r = *(const float2*)&Rbase[(size_t)bz*M*N + (size_t)m*N + n];
                        o.x += r.x; o.y += r.y;
                    }
                    *(float2*)((float*)Cbase + (size_t)bz*M*N + (size_t)m*N + n) = o;
                }
            }
        }
    }
}

// ---------------------------------------------------------------------------
// Flash attention: 128 queries/block, 4 warps, 2 q-tiles share K/V frags,
// 2-stage cp.async KV (smem 54.3KB -> 2 CTAs/SM = 2 warps/SMSP),
// f16 ex2 softmax, P in registers, ones-MMA row sums.
// ---------------------------------------------------------------------------
#define KSTR 72
#define QSTR2 136
#define OFF_KS (64*QSTR2)                      // 8704 halves
#define OFF_VS (OFF_KS + 2*64*KSTR)            // +9216
#define ATT_SMEM_HALVES (OFF_VS + 2*64*KSTR)   // 27136 halves
#define ATT_SMEM (ATT_SMEM_HALVES * 2)         // 54272 B  (<= 56.75KB for 2 CTAs)

__global__ __launch_bounds__(128, 2)
void attention_kernel(const __half* __restrict__ qkv,
                      __half* __restrict__ outp)
{
    extern __shared__ __align__(16) uint16_t sm[];
    uint16_t* Qs = sm;            // [64][136] — Q stage, then O stage
    uint16_t* Ks = sm + OFF_KS;   // [2][64][72]
    uint16_t* Vs = sm + OFF_VS;   // [2][64][72]

    int bh = blockIdx.y;
    int bb = bh >> 3, hh = bh & 7;
    int i0 = blockIdx.x * 128;
    const __half* qp = qkv + ((size_t)bb*3*CH + hh*HD) * HW_;
    const __half* kp = qp + (size_t)CH * HW_;
    const __half* vp = qp + (size_t)2*CH * HW_;

    int tid = threadIdx.x, lane = tid & 31, warp = tid >> 5;

    // prologue: group0 = Q + KV tile 0; group1 = KV tile 1
    #pragma unroll
    for (int r = 0; r < 8; r++) {
        int idx = r*128 + tid;
        int d = idx >> 4, cc = (idx & 15) * 8;
        cpa16(sptr(&Qs[d*QSTR2 + cc]), qp + (size_t)d*HW_ + i0 + cc);
    }
    #pragma unroll
    for (int r = 0; r < 4; r++) {
        int idx = r*128 + tid;
        int d = idx >> 3, cc = (idx & 7) * 8;
        cpa16(sptr(&Ks[d*KSTR + cc]), kp + (size_t)d*HW_ + cc);
        cpa16(sptr(&Vs[d*KSTR + cc]), vp + (size_t)d*HW_ + cc);
    }
    CP_COMMIT();
    #pragma unroll
    for (int r = 0; r < 4; r++) {
        int idx = r*128 + tid;
        int d = idx >> 3, cc = (idx & 7) * 8;
        cpa16(sptr(&Ks[64*KSTR + d*KSTR + cc]), kp + (size_t)d*HW_ + 64 + cc);
        cpa16(sptr(&Vs[64*KSTR + d*KSTR + cc]), vp + (size_t)d*HW_ + 64 + cc);
    }
    CP_COMMIT();

    const uint32_t ONE2 = 0x3C003C00u;           // half2(1,1)
    const uint32_t bones[2] = {ONE2, ONE2};

    uint32_t qf[2][4][4];
    float mx[2][2], l[2][2];
    float o[2][8][4];
    #pragma unroll
    for (int t = 0; t < 2; t++) {
        mx[t][0] = mx[t][1] = -1e30f;
        l[t][0] = l[t][1] = 0.f;
        #pragma unroll
        for (int nt = 0; nt < 8; nt++)
            #pragma unroll
            for (int e = 0; e < 4; e++) o[t][nt][e] = 0.f;
    }

    for (int jt = 0; jt < 16; jt++) {
        CP_WAIT(1);          // tile jt landed (committed 2+jt, need jt+1 done)
        __syncthreads();

        if (jt == 0) {   // Q frags (register-resident afterwards)
            int g = lane >> 3;
            int kq = (g >> 1)*8 + (lane & 7);
            #pragma unroll
            for (int t = 0; t < 2; t++) {
                int mq = t*64 + warp*16 + (g & 1)*8;
                #pragma unroll
                for (int ks = 0; ks < 4; ks++)
                    ldsm4t(qf[t][ks], sptr(&Qs[(ks*16 + kq)*QSTR2 + mq]));
            }
        }

        const uint16_t* Kc = Ks + (jt & 1)*64*KSTR;
        const uint16_t* Vc = Vs + (jt & 1)*64*KSTR;

        // S = Q K^T (both q-tiles share K frags)
        float s[2][8][4];
        #pragma unroll
        for (int t = 0; t < 2; t++)
            #pragma unroll
            for (int nt = 0; nt < 8; nt++)
                #pragma unroll
                for (int e = 0; e < 4; e++) s[t][nt][e] = 0.f;

        #pragma unroll
        for (int ks = 0; ks < 4; ks++) {
            int kk = ks*16 + (lane & 15);
            int cb = (lane >> 4)*8;
            #pragma unroll
            for (int ntp = 0; ntp < 4; ntp++) {
                uint32_t b[4];
                ldsm4t(b, sptr(&Kc[kk*KSTR + ntp*16 + cb]));
                #pragma unroll
                for (int t = 0; t < 2; t++) {
                    mma_f16(s[t][2*ntp],   qf[t][ks], &b[0]);
                    mma_f16(s[t][2*ntp+1], qf[t][ks], &b[2]);
                }
            }
        }

        // online softmax: rmax (fp32 + shfl), exp via ex2.f16x2 -> P frags
        uint32_t pah[2][4][4];
        #pragma unroll
        for (int t = 0; t < 2; t++) {
            float rmax0 = -1e30f, rmax1 = -1e30f;
            #pragma unroll
            for (int nt = 0; nt < 8; nt++) {
                rmax0 = fmaxf(rmax0, fmaxf(s[t][nt][0], s[t][nt][1]));
                rmax1 = fmaxf(rmax1, fmaxf(s[t][nt][2], s[t][nt][3]));
            }
            #pragma unroll
            for (int off = 1; off < 4; off <<= 1) {
                rmax0 = fmaxf(rmax0, __shfl_xor_sync(0xffffffffu, rmax0, off));
                rmax1 = fmaxf(rmax1, __shfl_xor_sync(0xffffffffu, rmax1, off));
            }
            float mn0 = fmaxf(mx[t][0], rmax0), mn1 = fmaxf(mx[t][1], rmax1);
            float corr0 = exp2f(mx[t][0] - mn0), corr1 = exp2f(mx[t][1] - mn1);
            mx[t][0] = mn0; mx[t][1] = mn1;

            #pragma unroll
            for (int nt = 0; nt < 8; nt++) {
                pah[t][nt >> 1][(nt & 1)*2 + 0] =
                    exp2h2(s[t][nt][0] - mn0, s[t][nt][1] - mn0);
                pah[t][nt >> 1][(nt & 1)*2 + 1] =
                    exp2h2(s[t][nt][2] - mn1, s[t][nt][3] - mn1);
            }

            float ls[4] = {0.f, 0.f, 0.f, 0.f};
            #pragma unroll
            for (int ks = 0; ks < 4; ks++)
                mma_f16(ls, pah[t][ks], bones);

            l[t][0] = l[t][0]*corr0 + ls[0];
            l[t][1] = l[t][1]*corr1 + ls[2];
            #pragma unroll
            for (int nt = 0; nt < 8; nt++) {
                o[t][nt][0] *= corr0; o[t][nt][1] *= corr0;
                o[t][nt][2] *= corr1; o[t][nt][3] *= corr1;
            }
        }

        // O += P @ V — P A-frags directly from f16x2 exp results
        #pragma unroll
        for (int ks = 0; ks < 4; ks++) {
            int jc = ks*16 + ((lane >> 3) & 1)*8;
            int dbase = (lane >> 4)*8 + (lane & 7);
            #pragma unroll
            for (int ntp = 0; ntp < 4; ntp++) {
                uint32_t b[4];
                ldsm4(b, sptr(&Vc[(ntp*16 + dbase)*KSTR + jc]));
                #pragma unroll
                for (int t = 0; t < 2; t++) {
                    mma_f16(o[t][2*ntp],   pah[t][ks], &b[0]);
                    mma_f16(o[t][2*ntp+1], pah[t][ks], &b[2]);
                }
            }
        }

        // second barrier: all reads of buf jt&1 finished block-wide before
        // cp.async overwrites it with tile jt+2
        __syncthreads();
        if (jt + 2 < 16) {
            int stp = (jt + 2) & 1;
            int j0 = (jt + 2) * 64;
            #pragma unroll
            for (int r = 0; r < 4; r++) {
                int idx = r*128 + tid;
                int d = idx >> 3, cc = (idx & 7) * 8;
                cpa16(sptr(&Ks[stp*64*KSTR + d*KSTR + cc]), kp + (size_t)d*HW_ + j0 + cc);
                cpa16(sptr(&Vs[stp*64*KSTR + d*KSTR + cc]), vp + (size_t)d*HW_ + j0 + cc);
            }
        }
        CP_COMMIT();
    }

    // normalize + stage O as fp16 [d][i] into Qs (Q long consumed)
    __syncthreads();
    {
        __half* Od = (__half*)Qs;
        #pragma unroll
        for (int t = 0; t < 2; t++) {
            float inv0 = 1.f / l[t][0], inv1 = 1.f / l[t][1];
            int iq = t*64 + warp*16 + (lane >> 2);
            #pragma unroll
            for (int nt = 0; nt < 8; nt++) {
                int d = nt*8 + 2*(lane & 3);
                Od[(size_t)d*QSTR2 + iq]         = __float2half_rn(o[t][nt][0]*inv0);
                Od[(size_t)(d+1)*QSTR2 + iq]     = __float2half_rn(o[t][nt][1]*inv0);
                Od[(size_t)d*QSTR2 + iq + 8]     = __float2half_rn(o[t][nt][2]*inv1);
                Od[(size_t)(d+1)*QSTR2 + iq + 8] = __float2half_rn(o[t][nt][3]*inv1);
            }
        }
    }
    __syncthreads();

    __half* ob = outp + ((size_t)bb*CH + hh*HD) * HW_;
    #pragma unroll
    for (int r = 0; r < 8; r++) {
        int idx = r*128 + tid;
        int d = idx >> 4, cc = (idx & 15) * 8;
        *(uint4*)&ob[(size_t)d*HW_ + i0 + cc] = *(const uint4*)&Qs[d*QSTR2 + cc];
    }
}

// ---------------------------------------------------------------------------
extern "C" void kernel_launch(void* const* d_in, const int* in_sizes, int n_in,
                              void* d_out, int out_size)
{
    const float* x      = (const float*)d_in[0];
    const float* gn_w   = (const float*)d_in[1];
    const float* gn_b   = (const float*)d_in[2];
    const float* qkv_w  = (const float*)d_in[3];
    const float* qkv_b  = (const float*)d_in[4];
    const float* proj_w = (const float*)d_in[5];
    const float* proj_b = (const float*)d_in[6];
    float* out = (float*)d_out;

    __half *xn, *qkvb, *att, *wq, *wp;
    cudaGetSymbolAddress((void**)&xn,   g_xn);
    cudaGetSymbolAddress((void**)&qkvb, g_qkv);
    cudaGetSymbolAddress((void**)&att,  g_att);
    cudaGetSymbolAddress((void**)&wq,   g_wq);
    cudaGetSymbolAddress((void**)&wp,   g_wp);

    cudaFuncSetAttribute(mma_gemm_kernel<true>,
                         cudaFuncAttributeMaxDynamicSharedMemorySize, GEMM_SMEM);
    cudaFuncSetAttribute(mma_gemm_kernel<false>,
                         cudaFuncAttributeMaxDynamicSharedMemorySize, GEMM_SMEM);
    cudaFuncSetAttribute(attention_kernel,
                         cudaFuncAttributeMaxDynamicSharedMemorySize, ATT_SMEM);

    // 0) weights fp32 -> fp16
    f2h_kernel<<<(3*CH*CH/4 + 255)/256, 256>>>(qkv_w, wq, 3*CH*CH);
    f2h_kernel<<<(CH*CH/4 + 255)/256, 256>>>(proj_w, wp, CH*CH);

    // 1) GroupNorm -> fp16
    groupnorm_kernel<<<BATCH*NGROUPS, 1024>>>(x, gn_w, gn_b, xn);

    // 2) qkv GEMM (fp16 out, q rows pre-scaled by 0.125*log2e)
    mma_gemm_kernel<true><<<dim3(HW_/GBN, (3*CH)/GBM, BATCH), 512, GEMM_SMEM>>>(
        wq, xn, qkvb, qkv_b, (const float*)0, 3*CH, CH, HW_, CH);

    // 3) flash attention (2-stage KV, 2 CTAs/SM)
    attention_kernel<<<dim3(HW_/128, BATCH*NH), 128, ATT_SMEM>>>(qkvb, att);

    // 4) proj GEMM (fp32 out + bias + residual)
    mma_gemm_kernel<false><<<dim3(HW_/GBN, CH/GBM, BATCH), 512, GEMM_SMEM>>>(
        wp, att, out, proj_b, x, CH, CH, HW_, 0);
}